// round 10
// baseline (speedup 1.0000x reference)
// BitLinear (rmsnorm -> ternary-quant weight -> GEMM -> scale) for GB300 sm_103a.
// tcgen05 unavailable (harness lowers via compute_103 -> ptxas rejects sm_103a
// features). Classic tensor-core path instead: mma.sync m16n8k16 f16->f32,
// 128x128x64 tiles, 3-stage cp.async pipeline, SW128 swizzle + ldmatrix.
#include <cuda_runtime.h>
#include <cuda_fp16.h>

#define M_TOT 8192
#define K_TOT 2048
#define N_TOT 8192
#define TM 128
#define TN 128
#define KC 64                                  // K elements per stage
#define STAGES 3
#define NKITER (K_TOT / KC)                    // 32
#define STAGE_BYTES ((TM + TN) * KC * 2)       // 32768 (A 16K + B 16K)
#define SMEM_GEMM (STAGES * STAGE_BYTES)       // 98304

// ---------------- scratch (device globals; no allocation allowed) ----------
__device__ __half g_xn[(size_t)M_TOT * K_TOT];   // rmsnorm(x) in fp16
__device__ __half g_wq[(size_t)N_TOT * K_TOT];   // ternary weights in fp16
__device__ float  g_partials[1024];
__device__ float  g_scale;

// ---------------- helpers ----------------
__device__ __forceinline__ unsigned smem_u32(const void* p) {
    unsigned a;
    asm("{ .reg .u64 t; cvta.to.shared.u64 t, %1; cvt.u32.u64 %0, t; }"
        : "=r"(a) : "l"(p));
    return a;
}

// ---------------- preprocessing kernels ----------------

// 1024 blocks x 256 thr, each block sums |w| over 16384 contiguous floats.
__global__ void absmean_partial(const float* __restrict__ w) {
    __shared__ float red[8];
    int t = threadIdx.x;
    const float4* p = reinterpret_cast<const float4*>(w) + (size_t)blockIdx.x * 4096;
    float s = 0.f;
#pragma unroll
    for (int i = 0; i < 16; i++) {
        float4 v = p[t + i * 256];
        s += fabsf(v.x) + fabsf(v.y) + fabsf(v.z) + fabsf(v.w);
    }
#pragma unroll
    for (int o = 16; o; o >>= 1) s += __shfl_xor_sync(~0u, s, o);
    if ((t & 31) == 0) red[t >> 5] = s;
    __syncthreads();
    if (t == 0) {
        float tot = 0.f;
#pragma unroll
        for (int i = 0; i < 8; i++) tot += red[i];
        g_partials[blockIdx.x] = tot;
    }
}

__global__ void absmean_final() {
    __shared__ float red[8];
    int t = threadIdx.x;
    float s = g_partials[t] + g_partials[t + 256] + g_partials[t + 512] + g_partials[t + 768];
#pragma unroll
    for (int o = 16; o; o >>= 1) s += __shfl_xor_sync(~0u, s, o);
    if ((t & 31) == 0) red[t >> 5] = s;
    __syncthreads();
    if (t == 0) {
        float tot = 0.f;
#pragma unroll
        for (int i = 0; i < 8; i++) tot += red[i];
        g_scale = fmaxf(tot * (1.0f / 16777216.0f), 1e-5f);
    }
}

// ternary quantize: wq = rint(clip(w/scale, -1, 1)) stored exactly in fp16
__global__ void quantize_w(const float* __restrict__ w) {
    size_t i = (size_t)blockIdx.x * blockDim.x + threadIdx.x;   // float4 index
    float s = g_scale;
    float4 v = reinterpret_cast<const float4*>(w)[i];
    float q0 = rintf(fminf(fmaxf(v.x / s, -1.f), 1.f));
    float q1 = rintf(fminf(fmaxf(v.y / s, -1.f), 1.f));
    float q2 = rintf(fminf(fmaxf(v.z / s, -1.f), 1.f));
    float q3 = rintf(fminf(fmaxf(v.w / s, -1.f), 1.f));
    __half2* o = reinterpret_cast<__half2*>(g_wq);
    o[2 * i]     = __floats2half2_rn(q0, q1);
    o[2 * i + 1] = __floats2half2_rn(q2, q3);
}

// rmsnorm each row of x (2048 wide), output fp16. One block per row.
__global__ void rmsnorm_k(const float* __restrict__ x, const float* __restrict__ gamma) {
    __shared__ float red[8];
    __shared__ float s_inv;
    int row = blockIdx.x, t = threadIdx.x;
    const float4* xr = reinterpret_cast<const float4*>(x + (size_t)row * K_TOT);
    float4 a = xr[t];
    float4 b = xr[t + 256];
    float ss = a.x * a.x + a.y * a.y + a.z * a.z + a.w * a.w
             + b.x * b.x + b.y * b.y + b.z * b.z + b.w * b.w;
#pragma unroll
    for (int o = 16; o; o >>= 1) ss += __shfl_xor_sync(~0u, ss, o);
    if ((t & 31) == 0) red[t >> 5] = ss;
    __syncthreads();
    if (t == 0) {
        float tot = 0.f;
#pragma unroll
        for (int i = 0; i < 8; i++) tot += red[i];
        s_inv = rsqrtf(tot * (1.0f / 2048.0f) + 1e-6f);
    }
    __syncthreads();
    float inv = s_inv;
    const float4* gr = reinterpret_cast<const float4*>(gamma);
    float4 ga = gr[t], gb = gr[t + 256];
    __half2* o2 = reinterpret_cast<__half2*>(g_xn + (size_t)row * K_TOT);
    o2[2 * t + 0] = __floats2half2_rn((a.x * inv) * ga.x, (a.y * inv) * ga.y);
    o2[2 * t + 1] = __floats2half2_rn((a.z * inv) * ga.z, (a.w * inv) * ga.w);
    o2[2 * (t + 256) + 0] = __floats2half2_rn((b.x * inv) * gb.x, (b.y * inv) * gb.y);
    o2[2 * (t + 256) + 1] = __floats2half2_rn((b.z * inv) * gb.z, (b.w * inv) * gb.w);
}

// ---------------- GEMM ----------------
// Stage layout: A tile [128 rows x 64 fp16] (128B rows, SW128 swizzle), then
// B tile [128 rows x 64 fp16] identically. 256 threads x 8 cp.async(16B)/stage.
__device__ __forceinline__ void load_stage(int tid, unsigned sS,
                                           const __half* Abase, const __half* Bbase,
                                           int kBase) {
#pragma unroll
    for (int i = 0; i < 8; i++) {
        int c = tid + i * 256;              // 0..2047; first 1024 chunks = A
        int cc = c & 1023;
        int row = cc >> 3;                  // 0..127
        int col16 = cc & 7;                 // 16B chunk within 128B row
        unsigned boff = (unsigned)((row << 7) | (col16 << 4));
        unsigned sw = boff ^ ((boff >> 3) & 0x70);
        unsigned saddr;
        const __half* g;
        if (c < 1024) { saddr = sS + sw;
                        g = Abase + (size_t)row * K_TOT + kBase + (col16 << 3); }
        else          { saddr = sS + (TM * KC * 2) + sw;
                        g = Bbase + (size_t)row * K_TOT + kBase + (col16 << 3); }
        asm volatile("cp.async.cg.shared.global [%0], [%1], 16;"
                     :: "r"(saddr), "l"(g) : "memory");
    }
}

__device__ __forceinline__ unsigned sw_addr(unsigned base, int row, int colBytes) {
    // row stride 128B, SW128: columns XOR'd by (row&7)<<4
    return base + (unsigned)(row << 7) + (unsigned)(colBytes ^ ((row & 7) << 4));
}

__global__ void __launch_bounds__(256) bitlinear_gemm(float* __restrict__ out) {
    extern __shared__ char smem[];
    unsigned sbase = smem_u32(smem);
    int tid = threadIdx.x;
    int wid = tid >> 5, lid = tid & 31;
    int warp_m = wid & 1;        // 2 warps along M, 64 rows each
    int warp_n = wid >> 1;       // 4 warps along N, 32 cols each

    // GROUP_M=8 tile swizzle for L2 reuse (64x64 tile grid)
    const int nPidN = N_TOT / TN;          // 64
    const int GROUP = 8;
    int pid = blockIdx.x;
    int perGrp = GROUP * nPidN;            // 512
    int firstM = (pid / perGrp) * GROUP;
    int inGrp = pid % perGrp;
    int mt = firstM + (inGrp % GROUP);
    int nt = inGrp / GROUP;

    const __half* Abase = g_xn + (size_t)mt * TM * K_TOT;
    const __half* Bbase = g_wq + (size_t)nt * TN * K_TOT;

    // prologue: 3 stages in flight
#pragma unroll
    for (int s = 0; s < STAGES; s++) {
        load_stage(tid, sbase + s * STAGE_BYTES, Abase, Bbase, s * KC);
        asm volatile("cp.async.commit_group;" ::: "memory");
    }

    float acc[4][4][4];                    // [mi][ni][frag]
#pragma unroll
    for (int mi = 0; mi < 4; mi++)
#pragma unroll
        for (int ni = 0; ni < 4; ni++)
#pragma unroll
            for (int j = 0; j < 4; j++) acc[mi][ni][j] = 0.f;

    for (int kt = 0; kt < NKITER; kt++) {
        unsigned aS = sbase + (kt % STAGES) * STAGE_BYTES;
        unsigned bS = aS + TM * KC * 2;
        if (kt <= NKITER - STAGES) asm volatile("cp.async.wait_group 2;" ::: "memory");
        else                       asm volatile("cp.async.wait_group 0;" ::: "memory");
        __syncthreads();

#pragma unroll
        for (int ks = 0; ks < KC / 16; ks++) {          // 4 k-steps of 16
            // A fragments: 4 tiles of 16x16 (ldmatrix.x4)
            unsigned a0[4], a1[4], a2[4], a3[4];
#pragma unroll
            for (int mi = 0; mi < 4; mi++) {
                int row = warp_m * 64 + mi * 16 + (lid & 15);
                int cb = ks * 32 + ((lid >> 4) << 4);
                unsigned addr = sw_addr(aS, row, cb);
                asm volatile("ldmatrix.sync.aligned.m8n8.x4.shared.b16 "
                             "{%0,%1,%2,%3}, [%4];"
                             : "=r"(a0[mi]), "=r"(a1[mi]), "=r"(a2[mi]), "=r"(a3[mi])
                             : "r"(addr));
            }
            // B fragments: 4 tiles of n8 x k16 (ldmatrix.x2, B^T layout [n][k])
            unsigned b0[4], b1[4];
#pragma unroll
            for (int ni = 0; ni < 4; ni++) {
                int q = lid & 15;
                int row = warp_n * 32 + ni * 8 + (q & 7);
                int cb = ks * 32 + ((q >> 3) << 4);
                unsigned addr = sw_addr(bS, row, cb);
                asm volatile("ldmatrix.sync.aligned.m8n8.x2.shared.b16 "
                             "{%0,%1}, [%2];"
                             : "=r"(b0[ni]), "=r"(b1[ni])
                             : "r"(addr));
            }
#pragma unroll
            for (int mi = 0; mi < 4; mi++)
#pragma unroll
                for (int ni = 0; ni < 4; ni++) {
                    asm volatile(
                        "mma.sync.aligned.m16n8k16.row.col.f32.f16.f16.f32 "
                        "{%0,%1,%2,%3}, {%4,%5,%6,%7}, {%8,%9}, {%0,%1,%2,%3};"
                        : "+f"(acc[mi][ni][0]), "+f"(acc[mi][ni][1]),
                          "+f"(acc[mi][ni][2]), "+f"(acc[mi][ni][3])
                        : "r"(a0[mi]), "r"(a1[mi]), "r"(a2[mi]), "r"(a3[mi]),
                          "r"(b0[ni]), "r"(b1[ni]));
                }
        }

        __syncthreads();                    // all warps done reading this stage
        int nk = kt + STAGES;
        if (nk < NKITER) {
            load_stage(tid, aS, Abase, Bbase, nk * KC);
            asm volatile("cp.async.commit_group;" ::: "memory");
        }
    }

    // ---------------- epilogue: scale + store (32B sector-aligned float2) ----
    float scl = g_scale;
    int mBase = mt * TM + warp_m * 64;
    int nBase = nt * TN + warp_n * 32;
    int rq = lid >> 2;                      // 0..7
    int cq = (lid & 3) * 2;                 // 0,2,4,6
#pragma unroll
    for (int mi = 0; mi < 4; mi++) {
#pragma unroll
        for (int ni = 0; ni < 4; ni++) {
            int col = nBase + ni * 8 + cq;
            float2 v0 = make_float2(acc[mi][ni][0] * scl, acc[mi][ni][1] * scl);
            float2 v1 = make_float2(acc[mi][ni][2] * scl, acc[mi][ni][3] * scl);
            *reinterpret_cast<float2*>(
                out + (size_t)(mBase + mi * 16 + rq) * N_TOT + col) = v0;
            *reinterpret_cast<float2*>(
                out + (size_t)(mBase + mi * 16 + rq + 8) * N_TOT + col) = v1;
        }
    }
}

// ---------------- launch ----------------
extern "C" void kernel_launch(void* const* d_in, const int* in_sizes, int n_in,
                              void* d_out, int out_size) {
    const float* x     = (const float*)d_in[0];   // [4,2048,2048]
    const float* w     = (const float*)d_in[1];   // [8192,2048]
    const float* gamma = (const float*)d_in[2];   // [2048]
    float* out = (float*)d_out;                   // [4,2048,8192] f32

    absmean_partial<<<1024, 256>>>(w);
    absmean_final<<<1, 256>>>();
    quantize_w<<<16384, 256>>>(w);
    rmsnorm_k<<<M_TOT, 256>>>(x, gamma);

    cudaFuncSetAttribute(bitlinear_gemm,
                         cudaFuncAttributeMaxDynamicSharedMemorySize, SMEM_GEMM);
    bitlinear_gemm<<<(M_TOT / TM) * (N_TOT / TN), 256, SMEM_GEMM>>>(out);
}